// round 17
// baseline (speedup 1.0000x reference)
#include <cuda_runtime.h>
#include <math.h>
#include <stdint.h>

// ---------------------------------------------------------------------------
// YoloLoss v7: TMA bulk-copy pipeline, 3 stages (v6 had 2).
//   - pred+tbox streamed per 128-cell tile via cp.async.bulk (copy-engine MLP)
//   - 3-stage ring: each refill gets 2 tile-computes of slack (kills the
//     wait-parity bubble that capped v6 at 4.46 TB/s)
//   - prologue TMAs issued before detection/obj-preload work
//   - tcls gated-scattered LDG (sparsity), obj preloaded x8
//   - warp-shuffle reduce -> 5 global f64 atomics -> last-block finalize
// ---------------------------------------------------------------------------

#define S_INV (1.0f / 14.0f)
#define TPB   128
#define TILE  128
#define NT    8                       // tiles per block
#define NSTG  3                       // pipeline stages

#define PRED_TILE_B (TILE * 30 * 4)   // 15360 bytes
#define TBOX_TILE_B (TILE * 4 * 4)    // 2048 bytes
#define TX_BYTES    (PRED_TILE_B + TBOX_TILE_B)

// acc[0]=n_obj, [1]=cls, [2]=noobj, [3]=reg, [4]=conf. Zero-initialized; the
// finalizing block restores them to zero (deterministic across graph replays).
__device__ double g_acc[5];
__device__ unsigned int g_done;

// ---- PTX helpers -----------------------------------------------------------
__device__ __forceinline__ unsigned smem_u32(const void* p) {
    return (unsigned)__cvta_generic_to_shared(p);
}
__device__ __forceinline__ unsigned long long gaddr(const void* p) {
    unsigned long long g;
    asm("cvta.to.global.u64 %0, %1;" : "=l"(g) : "l"(p));
    return g;
}
__device__ __forceinline__ void mbar_init(unsigned a, unsigned cnt) {
    asm volatile("mbarrier.init.shared.b64 [%0], %1;" :: "r"(a), "r"(cnt) : "memory");
}
__device__ __forceinline__ void mbar_expect_tx(unsigned a, unsigned bytes) {
    asm volatile("mbarrier.arrive.expect_tx.shared.b64 _, [%0], %1;"
                 :: "r"(a), "r"(bytes) : "memory");
}
__device__ __forceinline__ void bulk_g2s(unsigned dst, unsigned long long src,
                                         unsigned bytes, unsigned bar) {
    asm volatile(
        "cp.async.bulk.shared::cluster.global.mbarrier::complete_tx::bytes "
        "[%0], [%1], %2, [%3];"
        :: "r"(dst), "l"(src), "r"(bytes), "r"(bar) : "memory");
}
__device__ __forceinline__ void mbar_wait(unsigned a, unsigned phase) {
    unsigned done;
    asm volatile(
        "{\n\t.reg .pred p;\n\t"
        "mbarrier.try_wait.parity.acquire.cta.shared::cta.b64 p, [%1], %2;\n\t"
        "selp.b32 %0, 1, 0, p;\n\t}"
        : "=r"(done) : "r"(a), "r"(phase) : "memory");
    if (!done) {
        asm volatile(
            "{\n\t.reg .pred P1;\n\t"
            "W%=:\n\t"
            "mbarrier.try_wait.parity.acquire.cta.shared::cta.b64 P1, [%0], %1, 0x989680;\n\t"
            "@P1 bra.uni D%=;\n\t"
            "bra.uni W%=;\n\t"
            "D%=:\n\t}"
            :: "r"(a), "r"(phase) : "memory");
    }
}
__device__ __forceinline__ void fence_proxy_async_smem() {
    asm volatile("fence.proxy.async.shared::cta;" ::: "memory");
}

// ---- math -------------------------------------------------------------------
__device__ __forceinline__ float iou_xyxy(
    float x1, float y1, float x2, float y2,
    float tx1, float ty1, float tx2, float ty2)
{
    float lx = fmaxf(x1, tx1), ly = fmaxf(y1, ty1);
    float rx = fminf(x2, tx2), ry = fminf(y2, ty2);
    float w = fmaxf(rx - lx, 0.0f), h = fmaxf(ry - ly, 0.0f);
    float inter = w * h;
    float a1 = (x2 - x1) * (y2 - y1);
    float a2 = (tx2 - tx1) * (ty2 - ty1);
    return inter / (a1 + a2 - inter);
}

__device__ __forceinline__ void cell_compute(
    const float* __restrict__ prow, float4 tb,
    const float* __restrict__ tcrow, float obj,
    float& v_nobj, float& v_cls, float& v_noobj, float& v_reg, float& v_conf)
{
    float2 a0 = *(const float2*)(prow + 0);
    float2 a1 = *(const float2*)(prow + 2);
    float2 a2 = *(const float2*)(prow + 4);
    float2 a3 = *(const float2*)(prow + 6);
    float2 a4 = *(const float2*)(prow + 8);

    if (obj > 0.5f) {
        v_nobj += 1.0f;

        float tcx = tb.x * S_INV, tcy = tb.y * S_INV;
        float tx1 = tcx - 0.5f * tb.z, ty1 = tcy - 0.5f * tb.w;
        float tx2 = tcx + 0.5f * tb.z, ty2 = tcy + 0.5f * tb.w;

        float b1x = a0.x, b1y = a0.y, b1w = a1.x, b1h = a1.y, b1c = a2.x;
        float b2x = a2.y, b2y = a3.x, b2w = a3.y, b2h = a4.x, b2c = a4.y;

        float c1x = b1x * S_INV, c1y = b1y * S_INV;
        float c2x = b2x * S_INV, c2y = b2y * S_INV;

        float iou1 = iou_xyxy(c1x - 0.5f * b1w, c1y - 0.5f * b1h,
                              c1x + 0.5f * b1w, c1y + 0.5f * b1h,
                              tx1, ty1, tx2, ty2);
        float iou2 = iou_xyxy(c2x - 0.5f * b2w, c2y - 0.5f * b2h,
                              c2x + 0.5f * b2w, c2y + 0.5f * b2h,
                              tx1, ty1, tx2, ty2);

        bool take1 = (iou1 >= iou2);
        float bx = take1 ? b1x : b2x;
        float by = take1 ? b1y : b2y;
        float bw = take1 ? b1w : b2w;
        float bh = take1 ? b1h : b2h;
        float bc = take1 ? b1c : b2c;
        float biou = take1 ? iou1 : iou2;

        float dx = bx - tb.x;
        float dy = by - tb.y;
        float dw = sqrtf(bw) - sqrtf(tb.z);
        float dh = sqrtf(bh) - sqrtf(tb.w);
        v_reg += dx * dx + dy * dy + dw * dw + dh * dh;

        float dc = bc - biou;
        v_conf += dc * dc;

        const float2* pc = (const float2*)(prow + 10);
        const float4* tc = (const float4*)tcrow;
        float s = 0.0f;
        #pragma unroll
        for (int j = 0; j < 5; j++) {
            float4 t  = tc[j];
            float2 c0 = pc[2 * j];
            float2 c1 = pc[2 * j + 1];
            float d0 = c0.x - t.x, d1 = c0.y - t.y;
            float d2 = c1.x - t.z, d3 = c1.y - t.w;
            s += d0 * d0 + d1 * d1 + d2 * d2 + d3 * d3;
        }
        v_cls += s;
    } else {
        v_noobj += a0.x * a0.x + a0.y * a0.y + a1.x * a1.x + a1.y * a1.y
                 + a2.x * a2.x + a2.y * a2.y + a3.x * a3.x + a3.y * a3.y
                 + a4.x * a4.x + a4.y * a4.y;
    }
}

__global__ void __launch_bounds__(TPB)
yolo_fused(const float* __restrict__ pred,
           const float* __restrict__ tbox,
           const float* __restrict__ tcls,
           const void*  __restrict__ objp,
           float* __restrict__ out,
           int ncells, float Nf)
{
    __shared__ __align__(16) float sp[NSTG][TILE * 30];
    __shared__ __align__(16) float sb[NSTG][TILE * 4];
    __shared__ __align__(8)  unsigned long long mbar_store[NSTG];

    int tid = threadIdx.x;
    int ntiles_full = ncells / TILE;
    int tile0 = blockIdx.x * NT;

    unsigned mb0 = smem_u32(&mbar_store[0]);
    unsigned mb1 = smem_u32(&mbar_store[1]);
    unsigned mb2 = smem_u32(&mbar_store[2]);

    // ---- issue prologue TMAs IMMEDIATELY (engine streams during prefix work)
    if (tid == 0) {
        mbar_init(mb0, 1);
        mbar_init(mb1, 1);
        mbar_init(mb2, 1);
        fence_proxy_async_smem();
        #pragma unroll
        for (int s = 0; s < NSTG; s++) {
            int gt = tile0 + s;
            if (gt < ntiles_full && s < NT) {
                unsigned mbs = smem_u32(&mbar_store[s]);
                mbar_expect_tx(mbs, TX_BYTES);
                bulk_g2s(smem_u32(&sp[s][0]),
                         gaddr(pred + (size_t)gt * TILE * 30), PRED_TILE_B, mbs);
                bulk_g2s(smem_u32(&sb[s][0]),
                         gaddr(tbox + (size_t)gt * TILE * 4),  TBOX_TILE_B, mbs);
            }
        }
    }

    // ---- dtype detection from 2KB prefix (barriers publish mbar inits too) --
    //   float32 1.0f = 00 00 80 3F : byte with bits above 1     -> gt1
    //   uint8   0/1  : nonzero byte at offset %4 != 0           -> off4
    //   int32   0/1  : nonzero only at byte offset %4 == 0      -> neither
    unsigned v_all = 0;
    if ((tid + 1) * 16 <= ncells) {
        uint4 w = ((const uint4*)objp)[tid];
        v_all = w.x | w.y | w.z | w.w;
    }
    int gt1  = __syncthreads_or((v_all & 0xFEFEFEFEu) != 0);
    int off4 = __syncthreads_or((v_all & 0xFFFFFF00u) != 0);

    // ---- preload obj for all NT tiles (independent loads) -------------------
    float objv[NT];
    #pragma unroll
    for (int k = 0; k < NT; k++) {
        int i  = (tile0 + k) * TILE + tid;
        int ic = min(i, ncells - 1);
        if (gt1)       objv[k] = ((const float*)objp)[ic];
        else if (off4) objv[k] = (float)((const unsigned char*)objp)[ic];
        else           objv[k] = (float)((const int*)objp)[ic];
    }

    float v_nobj = 0.0f, v_cls = 0.0f, v_noobj = 0.0f, v_reg = 0.0f, v_conf = 0.0f;
    int fp0 = 0, fp1 = 0, fp2 = 0;    // per-stage phase bits

    #pragma unroll
    for (int t = 0; t < NT; t++) {
        int gt = tile0 + t;
        if (gt * TILE >= ncells) break;           // uniform across block
        int s = t % NSTG;

        if (gt < ntiles_full) {
            unsigned mbs = (s == 0) ? mb0 : (s == 1) ? mb1 : mb2;
            int ph = (s == 0) ? fp0 : (s == 1) ? fp1 : fp2;
            mbar_wait(mbs, ph);
            if (s == 0) fp0 ^= 1; else if (s == 1) fp1 ^= 1; else fp2 ^= 1;

            int i = gt * TILE + tid;
            float4 tb = ((const float4*)&sb[s][0])[tid];
            cell_compute(&sp[s][tid * 30], tb,
                         tcls + (size_t)i * 20, objv[t],
                         v_nobj, v_cls, v_noobj, v_reg, v_conf);

            __syncthreads();                      // all lanes done with stage s
            if (tid == 0) {
                int gt2 = gt + NSTG;
                if (t + NSTG < NT && gt2 < ntiles_full) {
                    fence_proxy_async_smem();
                    mbar_expect_tx(mbs, TX_BYTES);
                    bulk_g2s(smem_u32(&sp[s][0]),
                             gaddr(pred + (size_t)gt2 * TILE * 30), PRED_TILE_B, mbs);
                    bulk_g2s(smem_u32(&sb[s][0]),
                             gaddr(tbox + (size_t)gt2 * TILE * 4),  TBOX_TILE_B, mbs);
                }
            }
        } else {
            // ragged tail tile: direct global loads (cold path)
            int i = gt * TILE + tid;
            if (i < ncells) {
                float4 tb = ((const float4*)tbox)[i];
                cell_compute(pred + (size_t)i * 30, tb,
                             tcls + (size_t)i * 20, objv[t],
                             v_nobj, v_cls, v_noobj, v_reg, v_conf);
            }
        }
    }

    // ---- block reduction (4 warps, no smem atomics) --------------------------
    const unsigned m = 0xffffffffu;
    #pragma unroll
    for (int off = 16; off > 0; off >>= 1) {
        v_nobj  += __shfl_down_sync(m, v_nobj,  off);
        v_cls   += __shfl_down_sync(m, v_cls,   off);
        v_noobj += __shfl_down_sync(m, v_noobj, off);
        v_reg   += __shfl_down_sync(m, v_reg,   off);
        v_conf  += __shfl_down_sync(m, v_conf,  off);
    }

    __shared__ float swarp[4][8];
    int wid = tid >> 5;
    if ((tid & 31) == 0) {
        swarp[wid][0] = v_nobj;
        swarp[wid][1] = v_cls;
        swarp[wid][2] = v_noobj;
        swarp[wid][3] = v_reg;
        swarp[wid][4] = v_conf;
    }
    __syncthreads();

    if (tid < 5) {
        float s = swarp[0][tid] + swarp[1][tid] + swarp[2][tid] + swarp[3][tid];
        atomicAdd(&g_acc[tid], (double)s);
    }

    // ---- last-block finalize ---------------------------------------------------
    __threadfence();
    __shared__ unsigned int ticket;
    if (tid == 0) ticket = atomicAdd(&g_done, 1u);
    __syncthreads();
    if (ticket == gridDim.x - 1 && tid == 0) {
        __threadfence();
        double n_obj   = g_acc[0];
        double n_noobj = (double)ncells - n_obj;
        double cls   = g_acc[1] / (double)Nf;
        double noobj = 0.5 * g_acc[2] / n_noobj;
        double reg   = 5.0 * g_acc[3] / n_obj;
        double conf  = g_acc[4] / n_obj;
        out[0] = (float)(reg + conf + noobj + cls);
        out[1] = (float)reg;
        out[2] = (float)conf;
        out[3] = (float)noobj;
        out[4] = (float)cls;
        g_acc[0] = 0.0; g_acc[1] = 0.0; g_acc[2] = 0.0;
        g_acc[3] = 0.0; g_acc[4] = 0.0;
        g_done = 0u;
    }
}

extern "C" void kernel_launch(void* const* d_in, const int* in_sizes, int n_in,
                              void* d_out, int out_size)
{
    const float* pred = (const float*)d_in[0];
    const float* tbox = (const float*)d_in[1];
    const float* tcls = (const float*)d_in[2];
    const void*  objp = d_in[3];

    int ncells = in_sizes[1] / 4;                  // target_boxes: 4 floats/cell
    int nbatch = in_sizes[0] / (14 * 14 * 30);
    int ntiles = (ncells + TILE - 1) / TILE;       // 6272 for reference shape
    int nblocks = (ntiles + NT - 1) / NT;          // 784

    yolo_fused<<<nblocks, TPB>>>(pred, tbox, tcls, objp,
                                 (float*)d_out, ncells, (float)nbatch);
}